// round 13
// baseline (speedup 1.0000x reference)
#include <cuda_runtime.h>
#include <cuda_bf16.h>
#include <cstdint>

// Problem constants
#define NPIX   65536      // 64 * 32 * 32 pixels
#define HW     1024       // 32*32
#define CCH    10         // channels / token bits
#define NCODE  1024       // 2^10
#define NELEM  655360     // 64*10*32*32
#define NQUAD  (NPIX / 4) // 16384

// Output layout (flattened reference tuple, fp32)
#define OUT_SCALARS 655360
#define OUT_IDX     655365

// CQ = 400*log2(e);  CQH = CQ/2 (dot-trick halves the coefficient)
#define CQ   577.0780163555854f
#define CQH  288.5390081777927f
#define LN2  0.69314718055994531f

// Launch shapes
#define ABLK 256                      // signidx: 1 px / thread
#define ATHR 256
#define EBLK 444                      // entropy: 3 CTAs/SM on 148 SMs
#define ETHR 192                      // 6 warps/block -> 113-reg budget at occ 3
#define EWPB 6
#define NEWARPS (EBLK * EWPB)         // 2664 warps; grid-stride over pixel QUADS

typedef unsigned long long ull;

// Scratch (static __device__ — no allocations). Zero at module load;
// the finalizing block re-zeros for the next graph replay.
__device__ float g_avg_probs[NCODE];
__device__ float g_pse_sum;
__device__ float g_commit_parts[ABLK];
__device__ unsigned int g_done;

// ---------------- helpers ----------------
__device__ __forceinline__ float wred1(float a) {
#pragma unroll
    for (int o = 16; o; o >>= 1)
        a += __shfl_xor_sync(0xFFFFFFFFu, a, o);
    return a;
}
__device__ __forceinline__ void wred2(float& a, float& b) {
#pragma unroll
    for (int o = 16; o; o >>= 1) {
        a += __shfl_xor_sync(0xFFFFFFFFu, a, o);
        b += __shfl_xor_sync(0xFFFFFFFFu, b, o);
    }
}
__device__ __forceinline__ ull pk2(float a, float b) {
    ull r; asm("mov.b64 %0, {%1, %2};" : "=l"(r) : "f"(a), "f"(b)); return r;
}
__device__ __forceinline__ void upk2(ull v, float& a, float& b) {
    asm("mov.b64 {%0, %1}, %2;" : "=f"(a), "=f"(b) : "l"(v));
}
__device__ __forceinline__ ull addp(ull a, ull b) {
    ull r; asm("add.rn.f32x2 %0, %1, %2;" : "=l"(r) : "l"(a), "l"(b)); return r;
}
__device__ __forceinline__ ull mulp(ull a, ull b) {
    ull r; asm("mul.rn.f32x2 %0, %1, %2;" : "=l"(r) : "l"(a), "l"(b)); return r;
}
__device__ __forceinline__ ull fmap(ull a, ull b, ull c) {
    ull r; asm("fma.rn.f32x2 %0, %1, %2, %3;" : "=l"(r) : "l"(a), "l"(b), "l"(c)); return r;
}
__device__ __forceinline__ void ffma2(ull& acc, ull a, ull b) {
    asm("fma.rn.f32x2 %0, %1, %2, %0;" : "+l"(acc) : "l"(a), "l"(b));
}
__device__ __forceinline__ ull absp(ull v) { return v & 0x7FFFFFFF7FFFFFFFULL; }
__device__ __forceinline__ float ex2f(float x) {
    float r; asm("ex2.approx.f32 %0, %1;" : "=f"(r) : "f"(x)); return r;
}
__device__ __forceinline__ float rcpf(float x) {
    float r; asm("rcp.approx.f32 %0, %1;" : "=f"(r) : "f"(x)); return r;
}

// ---------------------------------------------------------------------------
// Kernel A: signs, indices, commitment partials. Block 0 zeros entropy scratch.
// ---------------------------------------------------------------------------
__global__ __launch_bounds__(ATHR) void lfq_signidx_kernel(
    const float* __restrict__ z, float* __restrict__ out)
{
    int tid = threadIdx.x;
    if (blockIdx.x == 0) {
        for (int i = tid; i < NCODE; i += ATHR) g_avg_probs[i] = 0.0f;
        if (tid == 0) g_pse_sum = 0.0f;
    }

    int p  = blockIdx.x * ATHR + tid;
    int b  = p >> 10;
    int hw = p & (HW - 1);
    const float* zp = z   + b * (CCH * HW) + hw;
    float*       op = out + b * (CCH * HW) + hw;

    int   idx  = 0;
    float csum = 0.0f;
#pragma unroll
    for (int c = 0; c < CCH; c++) {
        float v = __ldg(zp + c * HW);
        bool pos = v > 0.0f;
        op[c * HW] = pos ? 1.0f : -1.0f;
        idx |= (pos ? 1 : 0) << c;
        float d = 1.0f - fabsf(v);
        csum = fmaf(d, d, csum);
    }
    out[OUT_IDX + p] = (float)idx;

    csum = wred1(csum);
    __shared__ float s_red[ATHR / 32];
    if ((tid & 31) == 0) s_red[tid >> 5] = csum;
    __syncthreads();
    if (tid == 0) {
        float v = 0.0f;
#pragma unroll
        for (int w = 0; w < ATHR / 32; w++) v += s_red[w];
        g_commit_parts[blockIdx.x] = v;
    }
}

// ---------------------------------------------------------------------------
// Kernel B: entropy, 4 pixels (a quad) per iteration, packed f32x2 math.
//   code n = lo + 32*hi;  delta_n*log2e = b2[lo] + g2[hi], both <= 0, max 0
//   b2 = sum_c min(+-CQ*z_c, 0) = sum_c (+-CQH)*z_c - CQH*sum|z_c|  (dot trick)
//   Z = SB*SE;  T2/Z = S1/SB + S2/SE (deferred per-lane accumulation)
// ---------------------------------------------------------------------------
__global__ __launch_bounds__(ETHR, 3) void lfq_entropy_kernel(
    const float* __restrict__ z, float* __restrict__ out)
{
    __shared__ float s_ap[NCODE];
    __shared__ __align__(16) float s_x[EWPB][2][4][32];  // [warp][parity][px][lane]
    __shared__ float s_fred[EWPB];
    __shared__ float s_cred[EWPB];
    __shared__ unsigned int s_flag;

    int tid  = threadIdx.x;
    int lane = tid & 31;
    int w    = tid >> 5;
    for (int i = tid; i < NCODE; i += ETHR) s_ap[i] = 0.0f;
    __syncthreads();

    // packed per-lane sign constants: lane bit c picks +-CQH (same for c and c+5)
    ull sgn2[5];
#pragma unroll
    for (int c = 0; c < 5; c++) {
        float s = ((lane >> c) & 1) ? CQH : -CQH;
        sgn2[c] = pk2(s, s);
    }
    const ull NCQH2 = pk2(-CQH, -CQH);
    const ull C_P3  = pk2(-0.25f, -0.25f);
    const ull C_P2  = pk2(0.33333334f, 0.33333334f);
    const ull C_P1  = pk2(-0.5f, -0.5f);
    const ull C_P0  = pk2(1.0f, 1.0f);

    ull ap2[16];
#pragma unroll
    for (int k = 0; k < 16; k++) ap2[k] = 0ULL;
    float pse_lg = 0.0f;            // sum of ln(Z) (lane-uniform)
    ull x1_2 = 0ULL, x2_2 = 0ULL;   // packed deferred S1/SB, S2/SE partials
    int par = 0;

    int wid = blockIdx.x * EWPB + w;
    for (int q = wid; q < NQUAD; q += NEWARPS, par ^= 1) {
        int p0 = q << 2;                      // pixels p0..p0+3 (same batch row)
        int b  = p0 >> 10;
        int hw = p0 & (HW - 1);               // multiple of 4 -> float4 aligned
        const float4* zp = (const float4*)(z + b * (CCH * HW) + hw);

        // pair P = pixels (0,1), pair Q = pixels (2,3); packed f32x2 each
        ull dLP = 0, dHP = 0, aLP = 0, aHP = 0;
        ull dLQ = 0, dHQ = 0, aLQ = 0, aHQ = 0;
#pragma unroll
        for (int c = 0; c < 5; c++) {
            float4 v = __ldg(zp + c * (HW / 4));
            ull vP = pk2(v.x, v.y), vQ = pk2(v.z, v.w);
            dLP = fmap(vP, sgn2[c], dLP);  aLP = addp(aLP, absp(vP));
            dLQ = fmap(vQ, sgn2[c], dLQ);  aLQ = addp(aLQ, absp(vQ));
        }
#pragma unroll
        for (int c = 0; c < 5; c++) {
            float4 v = __ldg(zp + (c + 5) * (HW / 4));
            ull vP = pk2(v.x, v.y), vQ = pk2(v.z, v.w);
            dHP = fmap(vP, sgn2[c], dHP);  aHP = addp(aHP, absp(vP));
            dHQ = fmap(vQ, sgn2[c], dHQ);  aHQ = addp(aHQ, absp(vQ));
        }

        ull b2P = fmap(aLP, NCQH2, dLP);   // (b2 px0, b2 px1), both <= 0
        ull g2P = fmap(aHP, NCQH2, dHP);
        ull b2Q = fmap(aLQ, NCQH2, dLQ);
        ull g2Q = fmap(aHQ, NCQH2, dHQ);

        float b2a, b2b, g2a, g2b, b2c, b2d, g2c, g2d;
        upk2(b2P, b2a, b2b);  upk2(g2P, g2a, g2b);
        upk2(b2Q, b2c, b2d);  upk2(g2Q, g2c, g2d);

        float eba = ex2f(b2a), ebb = ex2f(b2b), ebc = ex2f(b2c), ebd = ex2f(b2d);
        float Eha = ex2f(g2a), Ehb = ex2f(g2b), Ehc = ex2f(g2c), Ehd = ex2f(g2d);

        // 8 interleaved butterfly chains: latencies overlap
        float SBa = eba, SEa = Eha, SBb = ebb, SEb = Ehb;
        float SBc = ebc, SEc = Ehc, SBd = ebd, SEd = Ehd;
#pragma unroll
        for (int o = 16; o; o >>= 1) {
            SBa += __shfl_xor_sync(0xFFFFFFFFu, SBa, o);
            SEa += __shfl_xor_sync(0xFFFFFFFFu, SEa, o);
            SBb += __shfl_xor_sync(0xFFFFFFFFu, SBb, o);
            SEb += __shfl_xor_sync(0xFFFFFFFFu, SEb, o);
            SBc += __shfl_xor_sync(0xFFFFFFFFu, SBc, o);
            SEc += __shfl_xor_sync(0xFFFFFFFFu, SEc, o);
            SBd += __shfl_xor_sync(0xFFFFFFFFu, SBd, o);
            SEd += __shfl_xor_sync(0xFFFFFFFFu, SEd, o);
        }

        float rSBa = rcpf(SBa), rSEa = rcpf(SEa);
        float rSBb = rcpf(SBb), rSEb = rcpf(SEb);
        float rSBc = rcpf(SBc), rSEc = rcpf(SEc);
        float rSBd = rcpf(SBd), rSEd = rcpf(SEd);

        float sa = fmaf(SBa, SEa, -1.0f);   // Z - 1 >= 0 (max term = exp(0))
        float sb = fmaf(SBb, SEb, -1.0f);
        float sc = fmaf(SBc, SEc, -1.0f);
        float sd = fmaf(SBd, SEd, -1.0f);

        float mx = fmaxf(fmaxf(sa, sb), fmaxf(sc, sd));
        if (mx < 0.0625f) {                 // packed ln(1+s) polynomial
            ull sP = pk2(sa, sb), sQ = pk2(sc, sd);
            ull tP = fmap(sP, C_P3, C_P2), tQ = fmap(sQ, C_P3, C_P2);
            tP = fmap(sP, tP, C_P1);        tQ = fmap(sQ, tQ, C_P1);
            tP = fmap(sP, tP, C_P0);        tQ = fmap(sQ, tQ, C_P0);
            ull rP = mulp(sP, tP), rQ = mulp(sQ, tQ);
            float r0, r1, r2, r3;
            upk2(rP, r0, r1);  upk2(rQ, r2, r3);
            pse_lg += (r0 + r1) + (r2 + r3);
        } else {
            pse_lg += logf(SBa * SEa) + logf(SBb * SEb)
                    + logf(SBc * SEc) + logf(SBd * SEd);
        }

        // deferred: T2/Z = S1/SB + S2/SE, per-lane packed accumulation (shared acc)
        ull ebP = pk2(eba, ebb), EhP = pk2(Eha, Ehb);
        ull ebQ = pk2(ebc, ebd), EhQ = pk2(Ehc, Ehd);
        x1_2 = fmap(mulp(ebP, b2P), pk2(rSBa, rSBb), x1_2);
        x2_2 = fmap(mulp(EhP, g2P), pk2(rSEa, rSEb), x2_2);
        x1_2 = fmap(mulp(ebQ, b2Q), pk2(rSBc, rSBd), x1_2);
        x2_2 = fmap(mulp(EhQ, g2Q), pk2(rSEc, rSEd), x2_2);

        float ua = eba * (rSBa * rSEa);     // eb * invZ
        float ub = ebb * (rSBb * rSEb);
        float uc = ebc * (rSBc * rSEc);
        float ud = ebd * (rSBd * rSEd);

        // avg_probs rank-1: ap[lane][j] += sum_px u_px * Eh_px[j]
        s_x[w][par][0][lane] = Eha;
        s_x[w][par][1][lane] = Ehb;
        s_x[w][par][2][lane] = Ehc;
        s_x[w][par][3][lane] = Ehd;
        __syncwarp();
        ull ua2 = pk2(ua, ua), ub2 = pk2(ub, ub);
        ull uc2 = pk2(uc, uc), ud2 = pk2(ud, ud);
        const ull* xa = (const ull*)s_x[w][par][0];
        const ull* xb = (const ull*)s_x[w][par][1];
        const ull* xc = (const ull*)s_x[w][par][2];
        const ull* xd = (const ull*)s_x[w][par][3];
#pragma unroll
        for (int k = 0; k < 16; k++) {
            ffma2(ap2[k], ua2, xa[k]);
            ffma2(ap2[k], ub2, xb[k]);
            ffma2(ap2[k], uc2, xc[k]);
            ffma2(ap2[k], ud2, xd[k]);
        }
        // no trailing syncwarp: parity double-buffer protects next iteration
    }

    // fold deferred partials: pse contribution = sum lg - LN2*(X1 + X2)
    float x1a, x1b, x2a, x2b;
    upk2(x1_2, x1a, x1b);
    upk2(x2_2, x2a, x2b);
    float x1 = x1a + x1b, x2 = x2a + x2b;
    wred2(x1, x2);
    if (lane == 0)
        atomicAdd(&g_pse_sum, pse_lg - LN2 * (x1 + x2));

    // flush avg_probs: smem atomics (bank = lane, conflict-free) -> global
#pragma unroll
    for (int k = 0; k < 16; k++) {
        float a, bv; upk2(ap2[k], a, bv);
        atomicAdd(&s_ap[(2 * k)     * 32 + lane], a);
        atomicAdd(&s_ap[(2 * k + 1) * 32 + lane], bv);
    }
    __syncthreads();
    for (int i = tid; i < NCODE; i += ETHR)
        atomicAdd(&g_avg_probs[i], s_ap[i]);

    // ---------------- last-block finalize ----------------
    __syncthreads();
    if (tid == 0) {
        __threadfence();
        s_flag = (atomicAdd(&g_done, 1u) == EBLK - 1) ? 1u : 0u;
    }
    __syncthreads();
    if (s_flag) {
        float local = 0.0f;
        for (int i = tid; i < NCODE; i += ETHR) {
            float ap = __ldcg(&g_avg_probs[i]) * (1.0f / (float)NPIX);
            local += ap * __logf(ap + 1e-5f);
        }
        local = wred1(local);
        if (lane == 0) s_fred[w] = local;
        float cpart = 0.0f;
        for (int i = tid; i < ABLK; i += ETHR) cpart += g_commit_parts[i];
        cpart = wred1(cpart);
        if (lane == 0) s_cred[w] = cpart;
        __syncthreads();
        if (tid == 0) {
            float v = 0.0f, cs = 0.0f;
#pragma unroll
            for (int i = 0; i < EWPB; i++) { v += s_fred[i]; cs += s_cred[i]; }
            float avg_ent = -v;
            float pse_m   = __ldcg(&g_pse_sum) * (1.0f / (float)NPIX);
            float commit  = 0.25f * cs * (1.0f / (float)NELEM);
            float ent_l   = 0.1f * (pse_m - avg_ent);
            out[OUT_SCALARS + 0] = commit + ent_l;   // loss
            out[OUT_SCALARS + 1] = commit;           // commitment_loss
            out[OUT_SCALARS + 2] = ent_l;            // entropy_loss
            out[OUT_SCALARS + 3] = pse_m;            // per_sample_entropy
            out[OUT_SCALARS + 4] = avg_ent;          // avg_entropy
        }
        // reset scratch for next graph replay
        for (int i = tid; i < NCODE; i += ETHR) __stcg(&g_avg_probs[i], 0.0f);
        if (tid == 0) {
            __stcg(&g_pse_sum, 0.0f);
            __threadfence();
            atomicExch(&g_done, 0u);
        }
    }
}

// ---------------------------------------------------------------------------
extern "C" void kernel_launch(void* const* d_in, const int* in_sizes, int n_in,
                              void* d_out, int out_size)
{
    const float* z   = (const float*)d_in[0];
    float*       out = (float*)d_out;
    (void)in_sizes; (void)n_in; (void)out_size;  // codebook implicit

    lfq_signidx_kernel<<<ABLK, ATHR>>>(z, out);
    lfq_entropy_kernel<<<EBLK, ETHR>>>(z, out);
}

// round 14
// speedup vs baseline: 1.0708x; 1.0708x over previous
#include <cuda_runtime.h>
#include <cuda_bf16.h>
#include <cstdint>

// Problem constants
#define NPIX   65536      // 64 * 32 * 32 pixels
#define HW     1024       // 32*32
#define CCH    10         // channels / token bits
#define NCODE  1024       // 2^10
#define NELEM  655360     // 64*10*32*32
#define NQUAD  (NPIX / 4) // 16384

// Output layout (flattened reference tuple, fp32)
#define OUT_SCALARS 655360
#define OUT_IDX     655365

// CQ = 400*log2(e);  CQH = CQ/2 (dot-trick halves the coefficient)
#define CQ   577.0780163555854f
#define CQH  288.5390081777927f
#define LN2  0.69314718055994531f

// Launch shapes
#define ABLK 512                      // signidx+pse: 1 px / thread, 128 thr
#define ATHR 128
#define EBLK 444                      // avg_probs: 3 CTAs/SM on 148 SMs
#define ETHR 256
#define EWPB 8
#define NEWARPS (EBLK * EWPB)         // 3552 warps; grid-stride over pixel QUADS

typedef unsigned long long ull;

// Scratch (static __device__ — no allocations). Zero at module load;
// the finalizing block re-zeros for the next graph replay.
__device__ float g_avg_probs[NCODE];
__device__ float g_pse_sum;
__device__ float g_commit_parts[ABLK];
__device__ alignas(16) float g_u[NPIX];   // per-pixel 1/Z
__device__ unsigned int g_done;

// ---------------- helpers ----------------
__device__ __forceinline__ float wred1(float a) {
#pragma unroll
    for (int o = 16; o; o >>= 1)
        a += __shfl_xor_sync(0xFFFFFFFFu, a, o);
    return a;
}
__device__ __forceinline__ ull pk2(float a, float b) {
    ull r; asm("mov.b64 %0, {%1, %2};" : "=l"(r) : "f"(a), "f"(b)); return r;
}
__device__ __forceinline__ void upk2(ull v, float& a, float& b) {
    asm("mov.b64 {%0, %1}, %2;" : "=f"(a), "=f"(b) : "l"(v));
}
__device__ __forceinline__ ull addp(ull a, ull b) {
    ull r; asm("add.rn.f32x2 %0, %1, %2;" : "=l"(r) : "l"(a), "l"(b)); return r;
}
__device__ __forceinline__ ull fmap(ull a, ull b, ull c) {
    ull r; asm("fma.rn.f32x2 %0, %1, %2, %3;" : "=l"(r) : "l"(a), "l"(b), "l"(c)); return r;
}
__device__ __forceinline__ void ffma2(ull& acc, ull a, ull b) {
    asm("fma.rn.f32x2 %0, %1, %2, %0;" : "+l"(acc) : "l"(a), "l"(b));
}
__device__ __forceinline__ ull absp(ull v) { return v & 0x7FFFFFFF7FFFFFFFULL; }
__device__ __forceinline__ float ex2f(float x) {
    float r; asm("ex2.approx.f32 %0, %1;" : "=f"(r) : "f"(x)); return r;
}
__device__ __forceinline__ float rcpf(float x) {
    float r; asm("rcp.approx.f32 %0, %1;" : "=f"(r) : "f"(x)); return r;
}

// ---------------------------------------------------------------------------
// Kernel A: thread-per-pixel. Signs, indices, commitment, AND the fully
// separable entropy pieces:
//   Z   = prod_c (1 + t_c),  t_c = 2^(-CQ*|z_c|)
//   pse = sum_c [ ln(1+t_c) + LN2*m_c*t_c/(1+t_c) ]
// Stores 1/Z per pixel for kernel B.
// ---------------------------------------------------------------------------
__global__ __launch_bounds__(ATHR) void lfq_signidx_kernel(
    const float* __restrict__ z, float* __restrict__ out)
{
    int tid = threadIdx.x;
    int p   = blockIdx.x * ATHR + tid;
    int b   = p >> 10;
    int hw  = p & (HW - 1);
    const float* zp = z   + b * (CCH * HW) + hw;
    float*       op = out + b * (CCH * HW) + hw;

    int   idx   = 0;
    float csum  = 0.0f;
    float prodZ = 1.0f;
    float pse_t = 0.0f;
#pragma unroll
    for (int c = 0; c < CCH; c++) {
        float v = __ldg(zp + c * HW);
        bool pos = v > 0.0f;
        op[c * HW] = pos ? 1.0f : -1.0f;
        idx |= (pos ? 1 : 0) << c;
        float a = fabsf(v);
        float d = 1.0f - a;
        csum = fmaf(d, d, csum);
        float m = CQ * a;                 // log2-domain mismatch penalty
        float t = ex2f(-m);               // underflows to 0 for most elements
        prodZ *= (1.0f + t);
        if (t > 1e-7f) {                  // skipped mass is < 1e-8 of pse
            float r = rcpf(1.0f + t);
            pse_t += __logf(1.0f + t) + (LN2 * m) * (t * r);
        }
    }
    out[OUT_IDX + p] = (float)idx;
    g_u[p] = rcpf(prodZ);                 // 1/Z for kernel B

    csum  = wred1(csum);
    pse_t = wred1(pse_t);
    __shared__ float s_red[ATHR / 32];
    __shared__ float s_pse[ATHR / 32];
    if ((tid & 31) == 0) {
        s_red[tid >> 5] = csum;
        s_pse[tid >> 5] = pse_t;
    }
    __syncthreads();
    if (tid == 0) {
        float v = 0.0f, ps = 0.0f;
#pragma unroll
        for (int w = 0; w < ATHR / 32; w++) { v += s_red[w]; ps += s_pse[w]; }
        g_commit_parts[blockIdx.x] = v;   // plain overwrite, no init needed
        atomicAdd(&g_pse_sum, ps);        // zeroed by last replay's finalizer
    }
}

// ---------------------------------------------------------------------------
// Kernel B: avg_probs only. Warp-per-pixel, 4 pixels (quad) per iteration.
//   code n = lo + 32*hi;  eb_lo = 2^(b2[lo]),  Eh_hi = 2^(g2[hi])
//   p_n = eb_lo * Eh_hi * invZ (invZ from kernel A — no reductions at all)
// ---------------------------------------------------------------------------
__global__ __launch_bounds__(ETHR, 3) void lfq_entropy_kernel(
    const float* __restrict__ z, float* __restrict__ out)
{
    __shared__ float s_ap[NCODE];
    __shared__ __align__(16) float s_x[EWPB][2][4][32];  // [warp][parity][px][lane]
    __shared__ float s_fred[EWPB];
    __shared__ float s_cred[EWPB];
    __shared__ unsigned int s_flag;

    int tid  = threadIdx.x;
    int lane = tid & 31;
    int w    = tid >> 5;
    for (int i = tid; i < NCODE; i += ETHR) s_ap[i] = 0.0f;
    __syncthreads();

    // packed per-lane sign constants: lane bit c picks +-CQH (same for c and c+5)
    ull sgn2[5];
#pragma unroll
    for (int c = 0; c < 5; c++) {
        float s = ((lane >> c) & 1) ? CQH : -CQH;
        sgn2[c] = pk2(s, s);
    }
    const ull NCQH2 = pk2(-CQH, -CQH);

    ull ap2[16];
#pragma unroll
    for (int k = 0; k < 16; k++) ap2[k] = 0ULL;
    int par = 0;

    int wid = blockIdx.x * EWPB + w;
    for (int q = wid; q < NQUAD; q += NEWARPS, par ^= 1) {
        int p0 = q << 2;                      // pixels p0..p0+3 (same batch row)
        int b  = p0 >> 10;
        int hw = p0 & (HW - 1);               // multiple of 4 -> float4 aligned
        const float4* zp = (const float4*)(z + b * (CCH * HW) + hw);
        float4 uz = __ldg((const float4*)(g_u + p0));   // invZ for 4 pixels

        // pair P = pixels (0,1), pair Q = pixels (2,3); packed f32x2 each
        ull dLP = 0, dHP = 0, aLP = 0, aHP = 0;
        ull dLQ = 0, dHQ = 0, aLQ = 0, aHQ = 0;
#pragma unroll
        for (int c = 0; c < 5; c++) {
            float4 v = __ldg(zp + c * (HW / 4));
            ull vP = pk2(v.x, v.y), vQ = pk2(v.z, v.w);
            dLP = fmap(vP, sgn2[c], dLP);  aLP = addp(aLP, absp(vP));
            dLQ = fmap(vQ, sgn2[c], dLQ);  aLQ = addp(aLQ, absp(vQ));
        }
#pragma unroll
        for (int c = 0; c < 5; c++) {
            float4 v = __ldg(zp + (c + 5) * (HW / 4));
            ull vP = pk2(v.x, v.y), vQ = pk2(v.z, v.w);
            dHP = fmap(vP, sgn2[c], dHP);  aHP = addp(aHP, absp(vP));
            dHQ = fmap(vQ, sgn2[c], dHQ);  aHQ = addp(aHQ, absp(vQ));
        }

        ull b2P = fmap(aLP, NCQH2, dLP);   // (b2 px0, b2 px1), both <= 0
        ull g2P = fmap(aHP, NCQH2, dHP);
        ull b2Q = fmap(aLQ, NCQH2, dLQ);
        ull g2Q = fmap(aHQ, NCQH2, dHQ);

        float b2a, b2b, g2a, g2b, b2c, b2d, g2c, g2d;
        upk2(b2P, b2a, b2b);  upk2(g2P, g2a, g2b);
        upk2(b2Q, b2c, b2d);  upk2(g2Q, g2c, g2d);

        float eba = ex2f(b2a), ebb = ex2f(b2b), ebc = ex2f(b2c), ebd = ex2f(b2d);
        float Eha = ex2f(g2a), Ehb = ex2f(g2b), Ehc = ex2f(g2c), Ehd = ex2f(g2d);

        float ua = eba * uz.x;             // eb * invZ — no reduction needed
        float ub = ebb * uz.y;
        float uc = ebc * uz.z;
        float ud = ebd * uz.w;

        // avg_probs rank-1: ap[lane][j] += sum_px u_px * Eh_px[j]
        s_x[w][par][0][lane] = Eha;
        s_x[w][par][1][lane] = Ehb;
        s_x[w][par][2][lane] = Ehc;
        s_x[w][par][3][lane] = Ehd;
        __syncwarp();
        ull ua2 = pk2(ua, ua), ub2 = pk2(ub, ub);
        ull uc2 = pk2(uc, uc), ud2 = pk2(ud, ud);
        const ull* xa = (const ull*)s_x[w][par][0];
        const ull* xb = (const ull*)s_x[w][par][1];
        const ull* xc = (const ull*)s_x[w][par][2];
        const ull* xd = (const ull*)s_x[w][par][3];
#pragma unroll
        for (int k = 0; k < 16; k++) {
            ffma2(ap2[k], ua2, xa[k]);
            ffma2(ap2[k], ub2, xb[k]);
            ffma2(ap2[k], uc2, xc[k]);
            ffma2(ap2[k], ud2, xd[k]);
        }
        // no trailing syncwarp: parity double-buffer protects next iteration
    }

    // flush avg_probs: smem atomics (bank = lane, conflict-free) -> global
#pragma unroll
    for (int k = 0; k < 16; k++) {
        float a, bv; upk2(ap2[k], a, bv);
        atomicAdd(&s_ap[(2 * k)     * 32 + lane], a);
        atomicAdd(&s_ap[(2 * k + 1) * 32 + lane], bv);
    }
    __syncthreads();
    for (int i = tid; i < NCODE; i += ETHR)
        atomicAdd(&g_avg_probs[i], s_ap[i]);

    // ---------------- last-block finalize ----------------
    __syncthreads();
    if (tid == 0) {
        __threadfence();
        s_flag = (atomicAdd(&g_done, 1u) == EBLK - 1) ? 1u : 0u;
    }
    __syncthreads();
    if (s_flag) {
        float local = 0.0f;
        for (int i = tid; i < NCODE; i += ETHR) {
            float ap = __ldcg(&g_avg_probs[i]) * (1.0f / (float)NPIX);
            local += ap * __logf(ap + 1e-5f);
        }
        local = wred1(local);
        if (lane == 0) s_fred[w] = local;
        float cpart = 0.0f;
        for (int i = tid; i < ABLK; i += ETHR) cpart += g_commit_parts[i];
        cpart = wred1(cpart);
        if (lane == 0) s_cred[w] = cpart;
        __syncthreads();
        if (tid == 0) {
            float v = 0.0f, cs = 0.0f;
#pragma unroll
            for (int i = 0; i < EWPB; i++) { v += s_fred[i]; cs += s_cred[i]; }
            float avg_ent = -v;
            float pse_m   = __ldcg(&g_pse_sum) * (1.0f / (float)NPIX);
            float commit  = 0.25f * cs * (1.0f / (float)NELEM);
            float ent_l   = 0.1f * (pse_m - avg_ent);
            out[OUT_SCALARS + 0] = commit + ent_l;   // loss
            out[OUT_SCALARS + 1] = commit;           // commitment_loss
            out[OUT_SCALARS + 2] = ent_l;            // entropy_loss
            out[OUT_SCALARS + 3] = pse_m;            // per_sample_entropy
            out[OUT_SCALARS + 4] = avg_ent;          // avg_entropy
        }
        // reset scratch for next graph replay
        for (int i = tid; i < NCODE; i += ETHR) __stcg(&g_avg_probs[i], 0.0f);
        if (tid == 0) {
            __stcg(&g_pse_sum, 0.0f);
            __threadfence();
            atomicExch(&g_done, 0u);
        }
    }
}

// ---------------------------------------------------------------------------
extern "C" void kernel_launch(void* const* d_in, const int* in_sizes, int n_in,
                              void* d_out, int out_size)
{
    const float* z   = (const float*)d_in[0];
    float*       out = (float*)d_out;
    (void)in_sizes; (void)n_in; (void)out_size;  // codebook implicit

    lfq_signidx_kernel<<<ABLK, ATHR>>>(z, out);
    lfq_entropy_kernel<<<EBLK, ETHR>>>(z, out);
}

// round 17
// speedup vs baseline: 1.1000x; 1.0273x over previous
#include <cuda_runtime.h>
#include <cuda_bf16.h>
#include <cstdint>

// Problem constants
#define NPIX   65536      // 64 * 32 * 32 pixels
#define HW     1024       // 32*32
#define CCH    10         // channels / token bits
#define NCODE  1024       // 2^10
#define NELEM  655360     // 64*10*32*32
#define NPAIR  (NPIX / 2) // 32768

// Output layout (flattened reference tuple, fp32)
#define OUT_SCALARS 655360
#define OUT_IDX     655365

// CQ = 400*log2(e);  CQH = CQ/2 (dot-trick halves the coefficient)
#define CQ   577.0780163555854f
#define CQH  288.5390081777927f
#define LN2  0.69314718055994531f

// Launch shapes
#define ABLK 512                      // signidx+pse: 1 px / thread, 128 thr
#define ATHR 128
#define EBLK 444                      // avg_probs: 3 CTAs/SM on 148 SMs
#define ETHR 256
#define EWPB 8
#define NEWARPS (EBLK * EWPB)         // 3552 warps; grid-stride over pixel PAIRS

typedef unsigned long long ull;

// Scratch (static __device__ — no allocations). Zero at module load;
// the finalizing block re-zeros for the next graph replay.
__device__ float g_avg_probs[NCODE];
__device__ float g_pse_sum;
__device__ float g_commit_parts[ABLK];
__device__ alignas(16) float g_u[NPIX];   // per-pixel 1/Z
__device__ unsigned int g_done;

// ---------------- helpers ----------------
__device__ __forceinline__ float wred1(float a) {
#pragma unroll
    for (int o = 16; o; o >>= 1)
        a += __shfl_xor_sync(0xFFFFFFFFu, a, o);
    return a;
}
__device__ __forceinline__ ull pk2(float a, float b) {
    ull r; asm("mov.b64 %0, {%1, %2};" : "=l"(r) : "f"(a), "f"(b)); return r;
}
__device__ __forceinline__ void upk2(ull v, float& a, float& b) {
    asm("mov.b64 {%0, %1}, %2;" : "=f"(a), "=f"(b) : "l"(v));
}
__device__ __forceinline__ ull addp(ull a, ull b) {
    ull r; asm("add.rn.f32x2 %0, %1, %2;" : "=l"(r) : "l"(a), "l"(b)); return r;
}
__device__ __forceinline__ ull fmap(ull a, ull b, ull c) {
    ull r; asm("fma.rn.f32x2 %0, %1, %2, %3;" : "=l"(r) : "l"(a), "l"(b), "l"(c)); return r;
}
__device__ __forceinline__ void ffma2(ull& acc, ull a, ull b) {
    asm("fma.rn.f32x2 %0, %1, %2, %0;" : "+l"(acc) : "l"(a), "l"(b));
}
__device__ __forceinline__ ull absp(ull v) { return v & 0x7FFFFFFF7FFFFFFFULL; }
__device__ __forceinline__ float ex2f(float x) {
    float r; asm("ex2.approx.f32 %0, %1;" : "=f"(r) : "f"(x)); return r;
}
__device__ __forceinline__ float rcpf(float x) {
    float r; asm("rcp.approx.f32 %0, %1;" : "=f"(r) : "f"(x)); return r;
}

// ---------------------------------------------------------------------------
// Kernel A: thread-per-pixel. Signs, indices, commitment, AND the fully
// separable entropy pieces:
//   Z   = prod_c (1 + t_c),  t_c = 2^(-CQ*|z_c|)
//   pse = sum_c [ ln(1+t_c) + LN2*m_c*t_c/(1+t_c) ]
// Stores 1/Z per pixel for kernel B.  (Validated in R13.)
// ---------------------------------------------------------------------------
__global__ __launch_bounds__(ATHR) void lfq_signidx_kernel(
    const float* __restrict__ z, float* __restrict__ out)
{
    int tid = threadIdx.x;
    int p   = blockIdx.x * ATHR + tid;
    int b   = p >> 10;
    int hw  = p & (HW - 1);
    const float* zp = z   + b * (CCH * HW) + hw;
    float*       op = out + b * (CCH * HW) + hw;

    int   idx   = 0;
    float csum  = 0.0f;
    float prodZ = 1.0f;
    float pse_t = 0.0f;
#pragma unroll
    for (int c = 0; c < CCH; c++) {
        float v = __ldg(zp + c * HW);
        bool pos = v > 0.0f;
        op[c * HW] = pos ? 1.0f : -1.0f;
        idx |= (pos ? 1 : 0) << c;
        float a = fabsf(v);
        float d = 1.0f - a;
        csum = fmaf(d, d, csum);
        float m = CQ * a;                 // log2-domain mismatch penalty
        float t = ex2f(-m);               // underflows to 0 for most elements
        prodZ *= (1.0f + t);
        if (t > 1e-7f) {                  // skipped mass is < 1e-8 of pse
            float r = rcpf(1.0f + t);
            pse_t += __logf(1.0f + t) + (LN2 * m) * (t * r);
        }
    }
    out[OUT_IDX + p] = (float)idx;
    g_u[p] = rcpf(prodZ);                 // 1/Z for kernel B

    csum  = wred1(csum);
    pse_t = wred1(pse_t);
    __shared__ float s_red[ATHR / 32];
    __shared__ float s_pse[ATHR / 32];
    if ((tid & 31) == 0) {
        s_red[tid >> 5] = csum;
        s_pse[tid >> 5] = pse_t;
    }
    __syncthreads();
    if (tid == 0) {
        float v = 0.0f, ps = 0.0f;
#pragma unroll
        for (int w = 0; w < ATHR / 32; w++) { v += s_red[w]; ps += s_pse[w]; }
        g_commit_parts[blockIdx.x] = v;   // plain overwrite, no init needed
        atomicAdd(&g_pse_sum, ps);        // zeroed by last replay's finalizer
    }
}

// ---------------------------------------------------------------------------
// Kernel B: avg_probs only. Warp-per-pixel, 2 pixels (a pair) per iteration.
//   code n = lo + 32*hi;  eb_lo = 2^(b2[lo]),  Eh_hi = 2^(g2[hi])
//   p_n = eb_lo * Eh_hi * invZ (invZ precomputed by A — NO reductions here)
// ---------------------------------------------------------------------------
__global__ __launch_bounds__(ETHR, 3) void lfq_entropy_kernel(
    const float* __restrict__ z, float* __restrict__ out)
{
    __shared__ float s_ap[NCODE];
    __shared__ __align__(16) float s_x[EWPB][2][2][32];  // [warp][parity][A/B][lane]
    __shared__ float s_fred[EWPB];
    __shared__ float s_cred[EWPB];
    __shared__ unsigned int s_flag;

    int tid  = threadIdx.x;
    int lane = tid & 31;
    int w    = tid >> 5;
    for (int i = tid; i < NCODE; i += ETHR) s_ap[i] = 0.0f;
    __syncthreads();

    // packed per-lane sign constants: lane bit c picks +-CQH (same for c and c+5)
    ull sgn2[5];
#pragma unroll
    for (int c = 0; c < 5; c++) {
        float s = ((lane >> c) & 1) ? CQH : -CQH;
        sgn2[c] = pk2(s, s);
    }
    const ull NCQH2 = pk2(-CQH, -CQH);

    ull ap2[16];
#pragma unroll
    for (int k = 0; k < 16; k++) ap2[k] = 0ULL;
    int par = 0;

    int wid = blockIdx.x * EWPB + w;
    for (int q = wid; q < NPAIR; q += NEWARPS, par ^= 1) {
        int p0 = q << 1;                      // pixels p0, p0+1 (same batch row)
        int b  = p0 >> 10;
        int hw = p0 & (HW - 1);               // even -> float2 aligned
        const float2* zp = (const float2*)(z + b * (CCH * HW) + hw);
        float2 uz = __ldg((const float2*)(g_u + p0));   // invZ for both pixels

        ull dL = 0, dH = 0, aL = 0, aH = 0;
#pragma unroll
        for (int c = 0; c < 5; c++) {
            float2 v = __ldg(zp + c * (HW / 2));
            ull v2 = pk2(v.x, v.y);
            dL = fmap(v2, sgn2[c], dL);
            aL = addp(aL, absp(v2));
        }
#pragma unroll
        for (int c = 0; c < 5; c++) {
            float2 v = __ldg(zp + (c + 5) * (HW / 2));
            ull v2 = pk2(v.x, v.y);
            dH = fmap(v2, sgn2[c], dH);
            aH = addp(aH, absp(v2));
        }

        ull b22 = fmap(aL, NCQH2, dL);        // (b2A, b2B), both <= 0
        ull g22 = fmap(aH, NCQH2, dH);        // (g2A, g2B)

        float b2A, b2B, g2A, g2B;
        upk2(b22, b2A, b2B);
        upk2(g22, g2A, g2B);
        float ebA = ex2f(b2A), ebB = ex2f(b2B);
        float EhA = ex2f(g2A), EhB = ex2f(g2B);

        float uA = ebA * uz.x;                // eb * invZ — no reduction needed
        float uB = ebB * uz.y;

        // avg_probs rank-1: ap[lane][j] += uA*EhA_j + uB*EhB_j
        s_x[w][par][0][lane] = EhA;
        s_x[w][par][1][lane] = EhB;
        __syncwarp();
        ull uA2 = pk2(uA, uA), uB2 = pk2(uB, uB);
        const ulonglong2* xa = (const ulonglong2*)s_x[w][par][0];
        const ulonglong2* xb = (const ulonglong2*)s_x[w][par][1];
#pragma unroll
        for (int k = 0; k < 8; k++) {         // LDS.128 broadcast reads
            ulonglong2 va = xa[k];
            ulonglong2 vb = xb[k];
            ffma2(ap2[2 * k],     uA2, va.x);
            ffma2(ap2[2 * k + 1], uA2, va.y);
            ffma2(ap2[2 * k],     uB2, vb.x);
            ffma2(ap2[2 * k + 1], uB2, vb.y);
        }
        // no trailing syncwarp: parity double-buffer protects next iteration
    }

    // flush avg_probs: smem atomics (bank = lane, conflict-free) -> global
#pragma unroll
    for (int k = 0; k < 16; k++) {
        float a, bv; upk2(ap2[k], a, bv);
        atomicAdd(&s_ap[(2 * k)     * 32 + lane], a);
        atomicAdd(&s_ap[(2 * k + 1) * 32 + lane], bv);
    }
    __syncthreads();
    for (int i = tid; i < NCODE; i += ETHR)
        atomicAdd(&g_avg_probs[i], s_ap[i]);

    // ---------------- last-block finalize ----------------
    __syncthreads();
    if (tid == 0) {
        __threadfence();
        s_flag = (atomicAdd(&g_done, 1u) == EBLK - 1) ? 1u : 0u;
    }
    __syncthreads();
    if (s_flag) {
        float local = 0.0f;
        for (int i = tid; i < NCODE; i += ETHR) {
            float ap = __ldcg(&g_avg_probs[i]) * (1.0f / (float)NPIX);
            local += ap * __logf(ap + 1e-5f);
        }
        local = wred1(local);
        if (lane == 0) s_fred[w] = local;
        float cpart = 0.0f;
        for (int i = tid; i < ABLK; i += ETHR) cpart += g_commit_parts[i];
        cpart = wred1(cpart);
        if (lane == 0) s_cred[w] = cpart;
        __syncthreads();
        if (tid == 0) {
            float v = 0.0f, cs = 0.0f;
#pragma unroll
            for (int i = 0; i < EWPB; i++) { v += s_fred[i]; cs += s_cred[i]; }
            float avg_ent = -v;
            float pse_m   = __ldcg(&g_pse_sum) * (1.0f / (float)NPIX);
            float commit  = 0.25f * cs * (1.0f / (float)NELEM);
            float ent_l   = 0.1f * (pse_m - avg_ent);
            out[OUT_SCALARS + 0] = commit + ent_l;   // loss
            out[OUT_SCALARS + 1] = commit;           // commitment_loss
            out[OUT_SCALARS + 2] = ent_l;            // entropy_loss
            out[OUT_SCALARS + 3] = pse_m;            // per_sample_entropy
            out[OUT_SCALARS + 4] = avg_ent;          // avg_entropy
        }
        // reset scratch for next graph replay
        for (int i = tid; i < NCODE; i += ETHR) __stcg(&g_avg_probs[i], 0.0f);
        if (tid == 0) {
            __stcg(&g_pse_sum, 0.0f);
            __threadfence();
            atomicExch(&g_done, 0u);
        }
    }
}

// ---------------------------------------------------------------------------
extern "C" void kernel_launch(void* const* d_in, const int* in_sizes, int n_in,
                              void* d_out, int out_size)
{
    const float* z   = (const float*)d_in[0];
    float*       out = (float*)d_out;
    (void)in_sizes; (void)n_in; (void)out_size;  // codebook implicit

    lfq_signidx_kernel<<<ABLK, ATHR>>>(z, out);
    lfq_entropy_kernel<<<EBLK, ETHR>>>(z, out);
}